// round 6
// baseline (speedup 1.0000x reference)
#include <cuda_runtime.h>

#define S 26
#define D 7
#define DA 11
#define V 29
#define NT (S * 32)   // 832 threads: one warp per sequence row

__global__ __launch_bounds__(NT, 1)
void bes_transformer_kernel(
    const int*   __restrict__ x,
    const float* __restrict__ emb_table,
    const float* __restrict__ pos,
    const float* __restrict__ wk0, const float* __restrict__ bk0,
    const float* __restrict__ wq0, const float* __restrict__ bq0,
    const float* __restrict__ wv0, const float* __restrict__ bv0,
    const float* __restrict__ wf0, const float* __restrict__ bf0,
    const float* __restrict__ wk1, const float* __restrict__ bk1,
    const float* __restrict__ wq1, const float* __restrict__ bq1,
    const float* __restrict__ wv1, const float* __restrict__ bv1,
    const float* __restrict__ wf1, const float* __restrict__ bf1,
    const float* __restrict__ wout, const float* __restrict__ bout,
    float* __restrict__ out)
{
    __shared__ float h0[S][D];
    __shared__ float h1[S][D];
    __shared__ float k0[S][DA], q0[S][DA], v0[S][DA];
    __shared__ float k1[S][DA], q1[S][DA], v1[S][DA];
    __shared__ float att[S][S];     // per-row private: reused across layers
    __shared__ float res[S][DA];    // per-row private: reused across layers
    __shared__ float inv_s[S];

    const int t    = threadIdx.x;
    const int r    = t >> 5;        // warp id == row id
    const int lane = t & 31;

    // ================= prefetch phase (all independent LDGs up front) ======
    int   xv = 0;
    float posv = 0.f;
    float wa[D], wb[D], wc[D];      // QKV weight rows (lanes 0-10: L0, 11-21: L1)
    float ba = 0.f, bb = 0.f, bc = 0.f;
    float wfr[DA], wf1r[DA];        // wf0 / wf1 rows (lanes 22-28)
    float bfv = 0.f, bf1v = 0.f;
    float wo[D];                    // wout row (lanes 0-28)
    float bo = 0.f;

    if (lane < D) { xv = x[r]; posv = pos[r * D + lane]; }

    if (lane < DA) {
        #pragma unroll
        for (int d = 0; d < D; d++) {
            wa[d] = wk0[lane * D + d];
            wb[d] = wq0[lane * D + d];
            wc[d] = wv0[lane * D + d];
        }
        ba = bk0[lane]; bb = bq0[lane]; bc = bv0[lane];
    } else if (lane < 2 * DA) {
        int a = lane - DA;
        #pragma unroll
        for (int d = 0; d < D; d++) {
            wa[d] = wk1[a * D + d];
            wb[d] = wq1[a * D + d];
            wc[d] = wv1[a * D + d];
        }
        ba = bk1[a]; bb = bq1[a]; bc = bv1[a];
    } else if (lane < 22 + D) {
        int d = lane - 22;
        #pragma unroll
        for (int a = 0; a < DA; a++) {
            wfr[a]  = wf0[d * DA + a];
            wf1r[a] = wf1[d * DA + a];
        }
        bfv = bf0[d]; bf1v = bf1[d];
    }
    if (lane < V) {
        #pragma unroll
        for (int d = 0; d < D; d++) wo[d] = wout[lane * D + d];
        bo = bout[lane];
    }

    // ================= stage 1: embedding + positional (own row) ==========
    if (lane < D) h0[r][lane] = emb_table[xv * D + lane] + posv;
    __syncwarp();

    // ================= stage 2: QKV layer 0 (lanes 0-10) ==================
    if (lane < DA) {
        float sk = ba, sq = bb, sv = bc;
        #pragma unroll
        for (int d = 0; d < D; d++) {
            float hv = h0[r][d];
            sk += hv * wa[d]; sq += hv * wb[d]; sv += hv * wc[d];
        }
        k0[r][lane] = sk; q0[r][lane] = sq; v0[r][lane] = sv;
    }
    __syncthreads();   // ===== BAR-A: k0/q0/v0 ready across all rows =====

    // ================= stage 3: scores layer 0 (lane c <= r) ==============
    if (lane <= r) {
        float s = 0.f;
        #pragma unroll
        for (int a = 0; a < DA; a++) s += q0[r][a] * k0[lane][a];
        att[r][lane] = __expf(s);
    }
    __syncwarp();

    // ================= stage 4: AV0 + normalize (lanes 0-10) ==============
    if (lane < DA) {
        float sum = 0.f, dot = 0.f;
        for (int c = 0; c <= r; c++) {
            float e = att[r][c];
            sum += e;
            dot += e * v0[c][lane];
        }
        res[r][lane] = dot * __frcp_rn(sum);
    }
    __syncwarp();

    // ================= stage 5: proj0 -> h1 (lanes 22-28) =================
    if (lane >= 22 && lane < 22 + D) {
        float val = bfv;
        #pragma unroll
        for (int a = 0; a < DA; a++) val += res[r][a] * wfr[a];
        h1[r][lane - 22] = val;
    }
    __syncwarp();

    // ================= stage 6: QKV layer 1 (lanes 11-21) =================
    if (lane >= DA && lane < 2 * DA) {
        int a = lane - DA;
        float sk = ba, sq = bb, sv = bc;
        #pragma unroll
        for (int d = 0; d < D; d++) {
            float hv = h1[r][d];
            sk += hv * wa[d]; sq += hv * wb[d]; sv += hv * wc[d];
        }
        k1[r][a] = sk; q1[r][a] = sq; v1[r][a] = sv;
    }
    __syncthreads();   // ===== BAR-B: k1/q1/v1 ready across all rows =====

    // ================= stage 7: scores layer 1 ============================
    if (lane <= r) {
        float s = 0.f;
        #pragma unroll
        for (int a = 0; a < DA; a++) s += q1[r][a] * k1[lane][a];
        att[r][lane] = __expf(s);
    }
    __syncwarp();

    // ================= stage 8: AV1 + normalize ===========================
    if (lane < DA) {
        float sum = 0.f, dot = 0.f;
        for (int c = 0; c <= r; c++) {
            float e = att[r][c];
            sum += e;
            dot += e * v1[c][lane];
        }
        float iv = __frcp_rn(sum);
        res[r][lane] = dot * iv;
        if (lane == 0) inv_s[r] = iv;
    }
    __syncwarp();

    // ================= stage 9: att output + proj1 (parallel roles) =======
    if (lane < S)
        out[S * V + r * S + lane] = (lane <= r) ? att[r][lane] * inv_s[r] : 0.f;
    if (lane >= 22 && lane < 22 + D) {
        float val = bf1v;
        #pragma unroll
        for (int a = 0; a < DA; a++) val += res[r][a] * wf1r[a];
        h1[r][lane - 22] = val;
    }
    __syncwarp();

    // ================= stage 10: logits for own row (lanes 0-28) ==========
    if (lane < V) {
        float val = bo;
        #pragma unroll
        for (int d = 0; d < D; d++) val += h1[r][d] * wo[d];
        out[r * V + lane] = val;
    }
}

extern "C" void kernel_launch(void* const* d_in, const int* in_sizes, int n_in,
                              void* d_out, int out_size)
{
    bes_transformer_kernel<<<1, NT>>>(
        (const int*)  d_in[0],   // x
        (const float*)d_in[1],   // emb_table
        (const float*)d_in[2],   // pos
        (const float*)d_in[3],  (const float*)d_in[4],   // w_k0, b_k0
        (const float*)d_in[5],  (const float*)d_in[6],   // w_q0, b_q0
        (const float*)d_in[7],  (const float*)d_in[8],   // w_v0, b_v0
        (const float*)d_in[9],  (const float*)d_in[10],  // w_f0, b_f0
        (const float*)d_in[11], (const float*)d_in[12],  // w_k1, b_k1
        (const float*)d_in[13], (const float*)d_in[14],  // w_q1, b_q1
        (const float*)d_in[15], (const float*)d_in[16],  // w_v1, b_v1
        (const float*)d_in[17], (const float*)d_in[18],  // w_f1, b_f1
        (const float*)d_in[19], (const float*)d_in[20],  // w_out, b_out
        (float*)d_out);
}

// round 7
// speedup vs baseline: 1.0034x; 1.0034x over previous
#include <cuda_runtime.h>

#define S 26
#define D 7
#define DA 11
#define V 29
#define NT (S * 32)   // 832 threads: one warp per sequence row

// smem weight-buffer offsets (floats)
#define P_WK0 0
#define P_BK0 77
#define P_WQ0 88
#define P_BQ0 165
#define P_WV0 176
#define P_BV0 253
#define P_WF0 264
#define P_BF0 341
#define P_WK1 348
#define P_BK1 425
#define P_WQ1 436
#define P_BQ1 513
#define P_WV1 524
#define P_BV1 601
#define P_WF1 612
#define P_BF1 689
#define P_WOUT 696
#define P_BOUT 899
#define P_TOTAL 928

#define CP(off, src, n) do { if (t < (n)) P[(off) + t] = (src)[t]; } while (0)

__global__ __launch_bounds__(NT, 1)
void bes_transformer_kernel(
    const int*   __restrict__ x,
    const float* __restrict__ emb_table,
    const float* __restrict__ pos,
    const float* __restrict__ wk0, const float* __restrict__ bk0,
    const float* __restrict__ wq0, const float* __restrict__ bq0,
    const float* __restrict__ wv0, const float* __restrict__ bv0,
    const float* __restrict__ wf0, const float* __restrict__ bf0,
    const float* __restrict__ wk1, const float* __restrict__ bk1,
    const float* __restrict__ wq1, const float* __restrict__ bq1,
    const float* __restrict__ wv1, const float* __restrict__ bv1,
    const float* __restrict__ wf1, const float* __restrict__ bf1,
    const float* __restrict__ wout, const float* __restrict__ bout,
    float* __restrict__ out)
{
    __shared__ float P[P_TOTAL];
    __shared__ float h0[S][D];
    __shared__ float h1[S][D];
    __shared__ float k0[S][DA], q0[S][DA], v0[S][DA];
    __shared__ float k1[S][DA], q1[S][DA], v1[S][DA];
    __shared__ float att[S][S];
    __shared__ float res[S][DA];
    __shared__ float inv_s[S];

    const int t    = threadIdx.x;
    const int r    = t >> 5;      // warp id == row id
    const int lane = t & 31;

    // ---- issue row-local global loads first (overlap with param copy) ----
    int   xv   = 0;
    float posv = 0.f;
    if (lane < D) { xv = x[r]; posv = pos[r * D + lane]; }

    // ---- cooperative coalesced copy of all weights into smem ----
    CP(P_WK0,  wk0,  DA * D);  CP(P_BK0,  bk0,  DA);
    CP(P_WQ0,  wq0,  DA * D);  CP(P_BQ0,  bq0,  DA);
    CP(P_WV0,  wv0,  DA * D);  CP(P_BV0,  bv0,  DA);
    CP(P_WF0,  wf0,  D * DA);  CP(P_BF0,  bf0,  D);
    CP(P_WK1,  wk1,  DA * D);  CP(P_BK1,  bk1,  DA);
    CP(P_WQ1,  wq1,  DA * D);  CP(P_BQ1,  bq1,  DA);
    CP(P_WV1,  wv1,  DA * D);  CP(P_BV1,  bv1,  DA);
    CP(P_WF1,  wf1,  D * DA);  CP(P_BF1,  bf1,  D);
    CP(P_WOUT, wout, V * D);   CP(P_BOUT, bout, V);

    // ---- embedding + positional (row-local, dependent gather) ----
    if (lane < D) h0[r][lane] = emb_table[xv * D + lane] + posv;
    __syncthreads();   // BAR-0: params in smem, h0 ready

    // ---- QKV layer 0: lane a computes k0/q0/v0[r][a] from smem ----
    if (lane < DA) {
        float sk = P[P_BK0 + lane], sq = P[P_BQ0 + lane], sv = P[P_BV0 + lane];
        #pragma unroll
        for (int d = 0; d < D; d++) {
            float hv = h0[r][d];
            sk += hv * P[P_WK0 + lane * D + d];
            sq += hv * P[P_WQ0 + lane * D + d];
            sv += hv * P[P_WV0 + lane * D + d];
        }
        k0[r][lane] = sk; q0[r][lane] = sq; v0[r][lane] = sv;
    }
    __syncthreads();   // BAR-A: k0/q0/v0 ready across all rows

    // ---- scores layer 0: lane c -> exp(q0[r].k0[c]) ----
    if (lane <= r) {
        float s = 0.f;
        #pragma unroll
        for (int a = 0; a < DA; a++) s += q0[r][a] * k0[lane][a];
        att[r][lane] = __expf(s);
    }
    __syncwarp();

    // ---- AV0 + normalize: lane a -> res[r][a] ----
    if (lane < DA) {
        float sum = 0.f, dot = 0.f;
        for (int c = 0; c <= r; c++) {
            float e = att[r][c];
            sum += e;
            dot += e * v0[c][lane];
        }
        res[r][lane] = dot * __frcp_rn(sum);
    }
    __syncwarp();

    // ---- proj0 -> h1: lane d ----
    if (lane < D) {
        float val = P[P_BF0 + lane];
        #pragma unroll
        for (int a = 0; a < DA; a++) val += res[r][a] * P[P_WF0 + lane * DA + a];
        h1[r][lane] = val;
    }
    __syncwarp();

    // ---- QKV layer 1: lane a ----
    if (lane < DA) {
        float sk = P[P_BK1 + lane], sq = P[P_BQ1 + lane], sv = P[P_BV1 + lane];
        #pragma unroll
        for (int d = 0; d < D; d++) {
            float hv = h1[r][d];
            sk += hv * P[P_WK1 + lane * D + d];
            sq += hv * P[P_WQ1 + lane * D + d];
            sv += hv * P[P_WV1 + lane * D + d];
        }
        k1[r][lane] = sk; q1[r][lane] = sq; v1[r][lane] = sv;
    }
    __syncthreads();   // BAR-B: k1/q1/v1 ready across all rows

    // ---- scores layer 1 ----
    if (lane <= r) {
        float s = 0.f;
        #pragma unroll
        for (int a = 0; a < DA; a++) s += q1[r][a] * k1[lane][a];
        att[r][lane] = __expf(s);
    }
    __syncwarp();

    // ---- AV1 + normalize ----
    if (lane < DA) {
        float sum = 0.f, dot = 0.f;
        for (int c = 0; c <= r; c++) {
            float e = att[r][c];
            sum += e;
            dot += e * v1[c][lane];
        }
        float iv = __frcp_rn(sum);
        res[r][lane] = dot * iv;
        if (lane == 0) inv_s[r] = iv;
    }
    __syncwarp();

    // ---- att output row (lanes 0-25) + proj1 (lanes 25-31) ----
    if (lane < S)
        out[S * V + r * S + lane] = (lane <= r) ? att[r][lane] * inv_s[r] : 0.f;
    if (lane >= 25 && lane < 25 + D) {
        int d = lane - 25;
        float val = P[P_BF1 + d];
        #pragma unroll
        for (int a = 0; a < DA; a++) val += res[r][a] * P[P_WF1 + d * DA + a];
        h1[r][d] = val;
    }
    __syncwarp();

    // ---- logits for own row: lane vv ----
    if (lane < V) {
        float val = P[P_BOUT + lane];
        #pragma unroll
        for (int d = 0; d < D; d++) val += h1[r][d] * P[P_WOUT + lane * D + d];
        out[r * V + lane] = val;
    }
}

extern "C" void kernel_launch(void* const* d_in, const int* in_sizes, int n_in,
                              void* d_out, int out_size)
{
    bes_transformer_kernel<<<1, NT>>>(
        (const int*)  d_in[0],   // x
        (const float*)d_in[1],   // emb_table
        (const float*)d_in[2],   // pos
        (const float*)d_in[3],  (const float*)d_in[4],   // w_k0, b_k0
        (const float*)d_in[5],  (const float*)d_in[6],   // w_q0, b_q0
        (const float*)d_in[7],  (const float*)d_in[8],   // w_v0, b_v0
        (const float*)d_in[9],  (const float*)d_in[10],  // w_f0, b_f0
        (const float*)d_in[11], (const float*)d_in[12],  // w_k1, b_k1
        (const float*)d_in[13], (const float*)d_in[14],  // w_q1, b_q1
        (const float*)d_in[15], (const float*)d_in[16],  // w_v1, b_v1
        (const float*)d_in[17], (const float*)d_in[18],  // w_f1, b_f1
        (const float*)d_in[19], (const float*)d_in[20],  // w_out, b_out
        (float*)d_out);
}

// round 8
// speedup vs baseline: 1.0391x; 1.0356x over previous
#include <cuda_runtime.h>

#define S 26
#define D 7
#define DA 11
#define V 29
#define NT 384
#define TRI (S*(S+1)/2)   // 351 lower-triangle elements

__global__ __launch_bounds__(NT, 1)
void bes_transformer_kernel(
    const int*   __restrict__ x,
    const float* __restrict__ emb_table,
    const float* __restrict__ pos,
    const float* __restrict__ wk0, const float* __restrict__ bk0,
    const float* __restrict__ wq0, const float* __restrict__ bq0,
    const float* __restrict__ wv0, const float* __restrict__ bv0,
    const float* __restrict__ wf0, const float* __restrict__ bf0,
    const float* __restrict__ wk1, const float* __restrict__ bk1,
    const float* __restrict__ wq1, const float* __restrict__ bq1,
    const float* __restrict__ wv1, const float* __restrict__ bv1,
    const float* __restrict__ wf1, const float* __restrict__ bf1,
    const float* __restrict__ wout, const float* __restrict__ bout,
    float* __restrict__ out)
{
    __shared__ float h[S][D];
    __shared__ float k[S][DA];
    __shared__ float q[S][DA];
    __shared__ float v[S][DA];
    __shared__ float att[S][S];   // upper triangle zeroed once, stays zero
    __shared__ float res[S][DA];
    __shared__ float inv_s[S];

    const int t = threadIdx.x;

    // packed-triangle coordinates for the score stages (t < TRI)
    int tr = 0, tc = 0;
    if (t < TRI) {
        tr = (int)((sqrtf(8.f * (float)t + 1.f) - 1.f) * 0.5f);
        if (t < tr * (tr + 1) / 2) tr--;           // fp safety
        if (t >= (tr + 1) * (tr + 2) / 2) tr++;
        tc = t - tr * (tr + 1) / 2;
    }

    // ---- stage 0: embedding + positional, and zero att ----
    if (t < S * D) {
        int s = t / D, d = t % D;
        h[s][d] = emb_table[x[s] * D + d] + pos[t];
    }
    for (int i = t; i < S * S; i += NT) att[i / S][i % S] = 0.f;
    __syncthreads();

    #pragma unroll 1
    for (int layer = 0; layer < 2; layer++) {
        const float* wk = layer ? wk1 : wk0;
        const float* bk = layer ? bk1 : bk0;
        const float* wq = layer ? wq1 : wq0;
        const float* bq = layer ? bq1 : bq0;
        const float* wv = layer ? wv1 : wv0;
        const float* bv = layer ? bv1 : bv0;
        const float* wf = layer ? wf1 : wf0;
        const float* bf = layer ? bf1 : bf0;

        // ---- QKV projections (286 elems, single shot) ----
        if (t < S * DA) {
            int s = t / DA, a = t % DA;
            float sk = bk[a], sq = bq[a], sv = bv[a];
            #pragma unroll
            for (int d = 0; d < D; d++) {
                float hv = h[s][d];
                sk += hv * wk[a * D + d];
                sq += hv * wq[a * D + d];
                sv += hv * wv[a * D + d];
            }
            k[s][a] = sk; q[s][a] = sq; v[s][a] = sv;
        }
        __syncthreads();

        // ---- scores: packed lower triangle, single shot ----
        if (t < TRI) {
            float sum = 0.f;
            #pragma unroll
            for (int a = 0; a < DA; a++) sum += q[tr][a] * k[tc][a];
            att[tr][tc] = __expf(sum);
        }
        __syncthreads();

        // ---- AV + normalize (286 elems, single shot, uniform 26-unrolled) ----
        if (t < S * DA) {
            int s = t / DA, a = t % DA;
            float sum = 0.f, dot = 0.f;
            #pragma unroll
            for (int c = 0; c < S; c++) {       // upper-tri att == 0
                float e = att[s][c];
                sum += e;
                dot += e * v[c][a];
            }
            float iv = __frcp_rn(sum);
            res[s][a] = dot * iv;
            if (a == 0) inv_s[s] = iv;
        }
        __syncthreads();

        // ---- h = res @ wf^T + bf (182 elems); layer-1 att out in parallel ----
        if (t < S * D) {
            int s = t / D, d = t % D;
            float r = bf[d];
            #pragma unroll
            for (int a = 0; a < DA; a++) r += res[s][a] * wf[d * DA + a];
            h[s][d] = r;
        }
        if (layer == 1) {
            for (int i = t; i < S * S; i += NT)
                out[S * V + i] = att[i / S][i % S] * inv_s[i / S];
        }
        __syncthreads();
    }

    // ---- logits: out = h @ wout^T + bout (754 elems, 2 shots) ----
    for (int i = t; i < S * V; i += NT) {
        int s = i / V, vv = i % V;
        float r = bout[vv];
        #pragma unroll
        for (int d = 0; d < D; d++) r += h[s][d] * wout[vv * D + d];
        out[i] = r;
    }
}

extern "C" void kernel_launch(void* const* d_in, const int* in_sizes, int n_in,
                              void* d_out, int out_size)
{
    bes_transformer_kernel<<<1, NT>>>(
        (const int*)  d_in[0],   // x
        (const float*)d_in[1],   // emb_table
        (const float*)d_in[2],   // pos
        (const float*)d_in[3],  (const float*)d_in[4],   // w_k0, b_k0
        (const float*)d_in[5],  (const float*)d_in[6],   // w_q0, b_q0
        (const float*)d_in[7],  (const float*)d_in[8],   // w_v0, b_v0
        (const float*)d_in[9],  (const float*)d_in[10],  // w_f0, b_f0
        (const float*)d_in[11], (const float*)d_in[12],  // w_k1, b_k1
        (const float*)d_in[13], (const float*)d_in[14],  // w_q1, b_q1
        (const float*)d_in[15], (const float*)d_in[16],  // w_v1, b_v1
        (const float*)d_in[17], (const float*)d_in[18],  // w_f1, b_f1
        (const float*)d_in[19], (const float*)d_in[20],  // w_out, b_out
        (float*)d_out);
}